// round 8
// baseline (speedup 1.0000x reference)
#include <cuda_runtime.h>
#include <cuda_bf16.h>
#include <math.h>
#include <stdint.h>

#define N_NODES 8192
#define NFEAT   512
#define NHID    256
#define NLAT    64
#define NCLASS  16
#define ALPHA   0.2f
#define NWORDS  (N_NODES / 32)

// ------------------------------ device scratch ------------------------------
__device__ __align__(16) float g_Wh1 [N_NODES * NHID];
__device__ __align__(16) float g_h   [N_NODES * NHID];
__device__ __align__(16) float g_Whmu[N_NODES * NLAT];
__device__ __align__(16) float g_Whlv[N_NODES * NLAT];
__device__ __align__(16) __nv_bfloat16 g_T1h[NHID * N_NODES];
__device__ __align__(16) __nv_bfloat16 g_T1l[NHID * N_NODES];
__device__ __align__(16) __nv_bfloat16 g_Tmh[NLAT * N_NODES];
__device__ __align__(16) __nv_bfloat16 g_Tml[NLAT * N_NODES];
__device__ __align__(16) __nv_bfloat16 g_Tvh[NLAT * N_NODES];
__device__ __align__(16) __nv_bfloat16 g_Tvl[NLAT * N_NODES];
__device__ unsigned g_adjb[(size_t)N_NODES * NWORDS];
__device__ float g_s1[N_NODES], g_d1[N_NODES];
__device__ float g_smu[N_NODES], g_dmu[N_NODES];
__device__ float g_slv[N_NODES], g_dlv[N_NODES];
__device__ __align__(16) float g_E1[N_NODES],  g_F1[N_NODES];
__device__ __align__(16) float g_Emu[N_NODES], g_Fmu[N_NODES];
__device__ __align__(16) float g_Elv[N_NODES], g_Flv[N_NODES];
__device__ unsigned g_dmaxu[4];
__device__ float    g_dmaxf[4];

// ------------------------------ helpers -------------------------------------
__device__ __forceinline__ uint32_t smem_u32(const void* p) {
    uint32_t a;
    asm("{ .reg .u64 t; cvta.to.shared.u64 t, %1; cvt.u32.u64 %0, t; }"
        : "=r"(a) : "l"(p));
    return a;
}
__device__ __forceinline__ void cp_async16(uint32_t dst, const void* src) {
    asm volatile("cp.async.cg.shared.global [%0], [%1], 16;"
                 :: "r"(dst), "l"(src) : "memory");
}
#define CP_COMMIT() asm volatile("cp.async.commit_group;" ::: "memory")
#define CP_WAIT1()  asm volatile("cp.async.wait_group 1;"  ::: "memory")
#define CP_WAIT0()  asm volatile("cp.async.wait_group 0;"  ::: "memory")

// order-preserving float->uint encoding for atomicMax
__device__ __forceinline__ unsigned fenc(float x) {
    int ix = __float_as_int(x);
    return ix >= 0 ? ((unsigned)ix | 0x80000000u) : ~(unsigned)ix;
}
__device__ __forceinline__ float fdec(unsigned u) {
    int ix = (u & 0x80000000u) ? (int)(u & 0x7FFFFFFFu) : ~(int)u;
    return __int_as_float(ix);
}

// mma.sync m16n8k16 row.col bf16 -> f32 (HMMA on sm_103)
__device__ __forceinline__ void mma16816(float* c,
    uint32_t a0, uint32_t a1, uint32_t a2, uint32_t a3,
    uint32_t b0, uint32_t b1)
{
    asm volatile(
        "mma.sync.aligned.m16n8k16.row.col.f32.bf16.bf16.f32 "
        "{%0,%1,%2,%3}, {%4,%5,%6,%7}, {%8,%9}, {%0,%1,%2,%3};"
        : "+f"(c[0]), "+f"(c[1]), "+f"(c[2]), "+f"(c[3])
        : "r"(a0), "r"(a1), "r"(a2), "r"(a3), "r"(b0), "r"(b1));
}

// ------------------------------ utility kernels -----------------------------
__global__ void init_kernel(unsigned* dmaxu)
{
    if (threadIdx.x < 4) dmaxu[threadIdx.x] = 0u;
}

__global__ __launch_bounds__(256)
void pack_adj_kernel(const int* __restrict__ adj, unsigned* __restrict__ bits)
{
    size_t idx = (size_t)blockIdx.x * 256 + threadIdx.x;
    int v = adj[idx] > 0;
    unsigned b = __ballot_sync(0xffffffffu, v);
    if ((threadIdx.x & 31) == 0) bits[idx >> 5] = b;
}

// transpose + bf16 hi/lo split: in[N][F] fp32 -> hiT/loT [F][N] bf16
__global__ __launch_bounds__(256)
void tsplit_kernel(const float* __restrict__ in,
                   __nv_bfloat16* __restrict__ hiT, __nv_bfloat16* __restrict__ loT,
                   int F)
{
    __shared__ float tile[32][33];
    int m0 = blockIdx.y * 32, f0 = blockIdx.x * 32;
    int x = threadIdx.x & 31, y = threadIdx.x >> 5;
    #pragma unroll
    for (int yy = 0; yy < 4; ++yy)
        tile[y + yy * 8][x] = in[(size_t)(m0 + y + yy * 8) * F + f0 + x];
    __syncthreads();
    #pragma unroll
    for (int yy = 0; yy < 4; ++yy) {
        float v = tile[x][y + yy * 8];
        __nv_bfloat16 hi = __float2bfloat16_rn(v);
        __nv_bfloat16 lo = __float2bfloat16_rn(v - __bfloat162float(hi));
        size_t o = (size_t)(f0 + y + yy * 8) * N_NODES + m0 + x;
        hiT[o] = hi; loT[o] = lo;
    }
}

// fp32 tiled GEMM: C = A(MxK) @ B(KxN)
__global__ __launch_bounds__(256)
void gemm_kernel(const float* __restrict__ A, const float* __restrict__ B,
                 float* __restrict__ C, int M, int N, int K)
{
    __shared__ float As[16][64];
    __shared__ float Bs[16][64];
    const int tid = threadIdx.x;
    const int tx = tid & 15, ty = tid >> 4;
    const int m0 = blockIdx.y * 64, n0 = blockIdx.x * 64;
    float acc[4][4] = {};
    for (int k0 = 0; k0 < K; k0 += 16) {
        {
            int m = tid >> 2, kq = (tid & 3) * 4;
            float4 v = *(const float4*)&A[(size_t)(m0 + m) * K + k0 + kq];
            As[kq + 0][m] = v.x; As[kq + 1][m] = v.y;
            As[kq + 2][m] = v.z; As[kq + 3][m] = v.w;
        }
        {
            int k = tid >> 4, nq = (tid & 15) * 4;
            *(float4*)&Bs[k][nq] = *(const float4*)&B[(size_t)(k0 + k) * N + n0 + nq];
        }
        __syncthreads();
        #pragma unroll
        for (int k = 0; k < 16; ++k) {
            float a[4], b[4];
            #pragma unroll
            for (int i = 0; i < 4; ++i) a[i] = As[k][ty * 4 + i];
            #pragma unroll
            for (int j = 0; j < 4; ++j) b[j] = Bs[k][tx * 4 + j];
            #pragma unroll
            for (int i = 0; i < 4; ++i)
                #pragma unroll
                for (int j = 0; j < 4; ++j)
                    acc[i][j] += a[i] * b[j];
        }
        __syncthreads();
    }
    #pragma unroll
    for (int i = 0; i < 4; ++i) {
        float4 v = make_float4(acc[i][0], acc[i][1], acc[i][2], acc[i][3]);
        *(float4*)&C[(size_t)(m0 + ty * 4 + i) * N + n0 + tx * 4] = v;
    }
}

// s/d projections + running max(d) via atomicMax
template <int F>
__global__ __launch_bounds__(256)
void sd_kernel(const float* __restrict__ Wh, const float* __restrict__ a,
               float* __restrict__ s, float* __restrict__ d,
               unsigned* __restrict__ dmaxu)
{
    int warp = (blockIdx.x * blockDim.x + threadIdx.x) >> 5;
    int lane = threadIdx.x & 31;
    if (warp >= N_NODES) return;
    const float* row = Wh + (size_t)warp * F;
    float ss = 0.f, dd = 0.f;
    #pragma unroll
    for (int f = lane; f < F; f += 32) {
        float w = row[f];
        ss += w * a[f];
        dd += w * a[F + f];
    }
    #pragma unroll
    for (int o = 16; o; o >>= 1) {
        ss += __shfl_down_sync(0xffffffffu, ss, o);
        dd += __shfl_down_sync(0xffffffffu, dd, o);
    }
    if (lane == 0) {
        s[warp] = ss; d[warp] = dd;
        atomicMax(dmaxu, fenc(dd));
    }
}

// E_j = exp(d_j - dmax), F_j = exp(alpha*(d_j - dmax)); also decode dmax->float
__global__ __launch_bounds__(256)
void ef_kernel(const float* __restrict__ d, const unsigned* __restrict__ dmaxu,
               float* __restrict__ E, float* __restrict__ F,
               float* __restrict__ dmaxf)
{
    float dm = fdec(*dmaxu);
    int i = blockIdx.x * 256 + threadIdx.x;
    float v = d[i] - dm;
    E[i] = __expf(v);
    F[i] = __expf(ALPHA * v);
    if (i == 0) *dmaxf = dm;
}

// =============================================================================
// attn1: h = ELU( softmax(mask(leaky(s_i+d_j))) @ Wh1 )   F=256, HMMA bf16x3
// CTA 64 rows, 256 threads (8 warps; warp w -> cols [32w,32w+32)).
// j-tile 64, double-buffered A/B smem, cp.async pipelined against MMA.
// Row pitch 144B (128B data + 16B pad) -> conflict-free fragment loads.
// =============================================================================
static constexpr int P1      = 144;
static constexpr int S1_B    = 0;          // 2 buf x [hi 256x144 | lo 256x144]
static constexpr int S1_BBUF = 73728;
static constexpr int S1_BLOO = 36864;
static constexpr int S1_A    = 147456;     // 2 buf x [hi 64x144 | lo 64x144]
static constexpr int S1_ABUF = 18432;
static constexpr int S1_ALOO = 9216;
static constexpr int S1_ZT   = 184320;     // 256 floats
static constexpr int S1_ZR   = 185344;     // 64 floats
static constexpr int SMEM1   = 185600;

__global__ __launch_bounds__(256, 1)
void attn1_kernel(const unsigned* __restrict__ adjb,
                  const __nv_bfloat16* __restrict__ Bh,
                  const __nv_bfloat16* __restrict__ Bl,
                  const float* __restrict__ svec, const float* __restrict__ dvec,
                  const float* __restrict__ EJ, const float* __restrict__ FJ,
                  const float* __restrict__ dmaxp, float* __restrict__ outp)
{
    extern __shared__ __align__(16) char smem[];
    const uint32_t sb = smem_u32(smem);
    const int tid = threadIdx.x, warp = tid >> 5, lane = tid & 31;
    const int g = lane >> 2, tq = lane & 3;
    const int i0 = blockIdx.x * 64;
    const int n0w = warp * 32;

    const int r = tid >> 2, q = tid & 3;
    const float sv = svec[i0 + r];
    const float mv = sv + *dmaxp;
    const float m_r = mv > 0.f ? mv : ALPHA * mv;
    const float RA = __expf(mv - m_r);
    const float RB = __expf(ALPHA * mv - m_r);
    float zacc = 0.f;

    float acc[4][4][4];
    #pragma unroll
    for (int a = 0; a < 4; ++a)
        #pragma unroll
        for (int b = 0; b < 4; ++b)
            #pragma unroll
            for (int c = 0; c < 4; ++c) acc[a][b][c] = 0.f;

    // B staging helper values
    const size_t row_adj = (size_t)(i0 + r) * NWORDS;

    // prologue: stage B tile 0 into buffer 0
    {
        const int j0 = 0;
        for (int c = tid; c < 4096; c += 256) {
            int mat = c >> 11, f = (c >> 3) & 255, ch = c & 7;
            uint32_t dst = sb + S1_B + mat * S1_BLOO + f * P1 + ch * 16;
            const __nv_bfloat16* src = (mat ? Bl : Bh) + (size_t)f * N_NODES + j0 + ch * 8;
            cp_async16(dst, src);
        }
    }
    CP_COMMIT();

    for (int t = 0; t < N_NODES / 64; ++t) {
        const int j0 = t * 64;
        const int buf = t & 1;

        // stage next tile into the other buffer
        if (t + 1 < N_NODES / 64) {
            const int j1 = j0 + 64;
            const uint32_t bb = sb + S1_B + (buf ^ 1) * S1_BBUF;
            for (int c = tid; c < 4096; c += 256) {
                int mat = c >> 11, f = (c >> 3) & 255, ch = c & 7;
                uint32_t dst = bb + mat * S1_BLOO + f * P1 + ch * 16;
                const __nv_bfloat16* src = (mat ? Bl : Bh) + (size_t)f * N_NODES + j1 + ch * 8;
                cp_async16(dst, src);
            }
        }
        CP_COMMIT();

        // ---- P-gen into A[buf]: thread covers (r, j in [q*16, q*16+16)) -----
        {
            unsigned w = adjb[row_adj + (j0 >> 5) + (q >> 1)];
            unsigned bits = w >> ((q & 1) * 16);
            char* ahi = smem + S1_A + buf * S1_ABUF + r * P1;
            char* alo = ahi + S1_ALOO;
            const int jb = q * 16;
            #pragma unroll
            for (int qq = 0; qq < 16; qq += 2) {
                int jl = jb + qq;
                int b0 = (bits >> qq) & 1;
                int b1 = (bits >> (qq + 1)) & 1;
                float d0 = dvec[j0 + jl], d1 = dvec[j0 + jl + 1];
                float p0 = b0 ? ((sv + d0 > 0.f) ? RA * EJ[j0 + jl]     : RB * FJ[j0 + jl])     : 0.f;
                float p1 = b1 ? ((sv + d1 > 0.f) ? RA * EJ[j0 + jl + 1] : RB * FJ[j0 + jl + 1]) : 0.f;
                zacc += p0 + p1;
                __nv_bfloat162 h2 = __floats2bfloat162_rn(p0, p1);
                float l0 = p0 - __bfloat162float(h2.x);
                float l1 = p1 - __bfloat162float(h2.y);
                __nv_bfloat162 lo2 = __floats2bfloat162_rn(l0, l1);
                *(__nv_bfloat162*)(ahi + jl * 2) = h2;
                *(__nv_bfloat162*)(alo + jl * 2) = lo2;
            }
        }

        CP_WAIT1();          // tile t staged; tile t+1 still in flight
        __syncthreads();     // A[buf] + B[buf] visible to all warps

        // ---- MMA on buffer buf ----------------------------------------------
        const int aoff = S1_A + buf * S1_ABUF;
        const int boff = S1_B + buf * S1_BBUF;
        #pragma unroll
        for (int kt = 0; kt < 4; ++kt) {
            const int koff = kt * 32 + tq * 4;
            uint32_t ah[4][4], al[4][4];
            #pragma unroll
            for (int mi = 0; mi < 4; ++mi) {
                const char* ba = smem + aoff + (mi * 16 + g) * P1 + koff;
                ah[mi][0] = *(const uint32_t*)(ba);
                ah[mi][1] = *(const uint32_t*)(ba + 8 * P1);
                ah[mi][2] = *(const uint32_t*)(ba + 16);
                ah[mi][3] = *(const uint32_t*)(ba + 8 * P1 + 16);
                const char* bl_ = ba + S1_ALOO;
                al[mi][0] = *(const uint32_t*)(bl_);
                al[mi][1] = *(const uint32_t*)(bl_ + 8 * P1);
                al[mi][2] = *(const uint32_t*)(bl_ + 16);
                al[mi][3] = *(const uint32_t*)(bl_ + 8 * P1 + 16);
            }
            #pragma unroll
            for (int ni = 0; ni < 4; ++ni) {
                const char* bb = smem + boff + (n0w + ni * 8 + g) * P1 + koff;
                uint32_t bh0 = *(const uint32_t*)(bb);
                uint32_t bh1 = *(const uint32_t*)(bb + 16);
                uint32_t bl0 = *(const uint32_t*)(bb + S1_BLOO);
                uint32_t bl1 = *(const uint32_t*)(bb + S1_BLOO + 16);
                #pragma unroll
                for (int mi = 0; mi < 4; ++mi) {
                    mma16816(acc[mi][ni], ah[mi][0], ah[mi][1], ah[mi][2], ah[mi][3], bh0, bh1);
                    mma16816(acc[mi][ni], ah[mi][0], ah[mi][1], ah[mi][2], ah[mi][3], bl0, bl1);
                    mma16816(acc[mi][ni], al[mi][0], al[mi][1], al[mi][2], al[mi][3], bh0, bh1);
                }
            }
        }
        __syncthreads();     // all reads of buf done before it is restaged
    }

    // ---- epilogue: Z-normalize, ELU, store ------------------------------------
    float* zt = (float*)(smem + S1_ZT);
    float* zr = (float*)(smem + S1_ZR);
    zt[tid] = zacc;
    __syncthreads();
    if (tid < 64)
        zr[tid] = zt[4 * tid] + zt[4 * tid + 1] + zt[4 * tid + 2] + zt[4 * tid + 3];
    __syncthreads();
    #pragma unroll
    for (int mi = 0; mi < 4; ++mi) {
        int r0 = mi * 16 + g;
        float iz0 = 1.f / zr[r0];
        float iz1 = 1.f / zr[r0 + 8];
        #pragma unroll
        for (int ni = 0; ni < 4; ++ni) {
            int col = n0w + ni * 8 + tq * 2;
            float v0 = acc[mi][ni][0] * iz0; v0 = v0 > 0.f ? v0 : expm1f(v0);
            float v1 = acc[mi][ni][1] * iz0; v1 = v1 > 0.f ? v1 : expm1f(v1);
            float v2 = acc[mi][ni][2] * iz1; v2 = v2 > 0.f ? v2 : expm1f(v2);
            float v3 = acc[mi][ni][3] * iz1; v3 = v3 > 0.f ? v3 : expm1f(v3);
            *(float2*)&outp[(size_t)(i0 + r0) * NHID + col]     = make_float2(v0, v1);
            *(float2*)&outp[(size_t)(i0 + r0 + 8) * NHID + col] = make_float2(v2, v3);
        }
    }
}

// =============================================================================
// attn23: fused mu & lv attention, F=64 each. 256 threads.
// warps 0-3: mu cols [16w..16w+16); warps 4-7: lv.
// =============================================================================
static constexpr int S2_B    = 0;          // 2 buf x 4 mats x 64x144
static constexpr int S2_BBUF = 36864;
static constexpr int S2_A    = 73728;      // 2 buf x 4 mats x 64x144
static constexpr int S2_ABUF = 36864;
static constexpr int S2_MAT  = 9216;
static constexpr int S2_ZT   = 147456;     // 2 x 256 floats
static constexpr int S2_ZR   = 149504;     // 2 x 64 floats
static constexpr int SMEM2   = 150016;

__global__ __launch_bounds__(256, 1)
void attn23_kernel(const unsigned* __restrict__ adjb,
                   const __nv_bfloat16* __restrict__ Bmh, const __nv_bfloat16* __restrict__ Bml,
                   const __nv_bfloat16* __restrict__ Bvh, const __nv_bfloat16* __restrict__ Bvl,
                   const float* __restrict__ smuv, const float* __restrict__ dmuv,
                   const float* __restrict__ slvv, const float* __restrict__ dlvv,
                   const float* __restrict__ Em, const float* __restrict__ Fm,
                   const float* __restrict__ Ev, const float* __restrict__ Fv,
                   const float* __restrict__ dmaxp,   // [0]=mu, [1]=lv
                   float* __restrict__ out_mu, float* __restrict__ out_lv)
{
    extern __shared__ __align__(16) char smem[];
    const uint32_t sb = smem_u32(smem);
    const int tid = threadIdx.x, warp = tid >> 5, lane = tid & 31;
    const int g = lane >> 2, tq = lane & 3;
    const int i0 = blockIdx.x * 64;
    const int which = warp >> 2;          // 0 = mu, 1 = lv
    const int n0w = (warp & 3) * 16;

    const int r = tid >> 2, q = tid & 3;
    const float svm = smuv[i0 + r], svv = slvv[i0 + r];
    const float mvm = svm + dmaxp[0], mvv = svv + dmaxp[1];
    const float mm = mvm > 0.f ? mvm : ALPHA * mvm;
    const float ml = mvv > 0.f ? mvv : ALPHA * mvv;
    const float RAm = __expf(mvm - mm), RBm = __expf(ALPHA * mvm - mm);
    const float RAv = __expf(mvv - ml), RBv = __expf(ALPHA * mvv - ml);
    float zm = 0.f, zv = 0.f;

    float acc[4][2][4];
    #pragma unroll
    for (int a = 0; a < 4; ++a)
        #pragma unroll
        for (int b = 0; b < 2; ++b)
            #pragma unroll
            for (int c = 0; c < 4; ++c) acc[a][b][c] = 0.f;

    const size_t row_adj = (size_t)(i0 + r) * NWORDS;

    // prologue: stage B tile 0 into buffer 0
    for (int c = tid; c < 2048; c += 256) {
        int mat = c >> 9, f = (c >> 3) & 63, ch = c & 7;
        uint32_t dst = sb + S2_B + mat * S2_MAT + f * P1 + ch * 16;
        const __nv_bfloat16* src = (mat == 0 ? Bmh : mat == 1 ? Bml : mat == 2 ? Bvh : Bvl)
                                   + (size_t)f * N_NODES + ch * 8;
        cp_async16(dst, src);
    }
    CP_COMMIT();

    for (int t = 0; t < N_NODES / 64; ++t) {
        const int j0 = t * 64;
        const int buf = t & 1;

        if (t + 1 < N_NODES / 64) {
            const int j1 = j0 + 64;
            const uint32_t bbs = sb + S2_B + (buf ^ 1) * S2_BBUF;
            for (int c = tid; c < 2048; c += 256) {
                int mat = c >> 9, f = (c >> 3) & 63, ch = c & 7;
                uint32_t dst = bbs + mat * S2_MAT + f * P1 + ch * 16;
                const __nv_bfloat16* src = (mat == 0 ? Bmh : mat == 1 ? Bml : mat == 2 ? Bvh : Bvl)
                                           + (size_t)f * N_NODES + j1 + ch * 8;
                cp_async16(dst, src);
            }
        }
        CP_COMMIT();

        // ---- P-gen: both matrices, thread covers (r, j in [q*16,q*16+16)) ---
        {
            unsigned w = adjb[row_adj + (j0 >> 5) + (q >> 1)];
            unsigned bits = w >> ((q & 1) * 16);
            char* amh = smem + S2_A + buf * S2_ABUF + r * P1;
            char* aml = amh + S2_MAT;
            char* avh = amh + 2 * S2_MAT;
            char* avl = amh + 3 * S2_MAT;
            const int jb = q * 16;
            #pragma unroll
            for (int qq = 0; qq < 16; qq += 2) {
                int jl = jb + qq;
                int b0 = (bits >> qq) & 1;
                int b1 = (bits >> (qq + 1)) & 1;

                float d0 = dmuv[j0 + jl], d1 = dmuv[j0 + jl + 1];
                float p0 = b0 ? ((svm + d0 > 0.f) ? RAm * Em[j0 + jl]     : RBm * Fm[j0 + jl])     : 0.f;
                float p1 = b1 ? ((svm + d1 > 0.f) ? RAm * Em[j0 + jl + 1] : RBm * Fm[j0 + jl + 1]) : 0.f;
                zm += p0 + p1;
                __nv_bfloat162 h2 = __floats2bfloat162_rn(p0, p1);
                __nv_bfloat162 l2 = __floats2bfloat162_rn(p0 - __bfloat162float(h2.x),
                                                          p1 - __bfloat162float(h2.y));
                *(__nv_bfloat162*)(amh + jl * 2) = h2;
                *(__nv_bfloat162*)(aml + jl * 2) = l2;

                d0 = dlvv[j0 + jl]; d1 = dlvv[j0 + jl + 1];
                p0 = b0 ? ((svv + d0 > 0.f) ? RAv * Ev[j0 + jl]     : RBv * Fv[j0 + jl])     : 0.f;
                p1 = b1 ? ((svv + d1 > 0.f) ? RAv * Ev[j0 + jl + 1] : RBv * Fv[j0 + jl + 1]) : 0.f;
                zv += p0 + p1;
                h2 = __floats2bfloat162_rn(p0, p1);
                l2 = __floats2bfloat162_rn(p0 - __bfloat162float(h2.x),
                                           p1 - __bfloat162float(h2.y));
                *(__nv_bfloat162*)(avh + jl * 2) = h2;
                *(__nv_bfloat162*)(avl + jl * 2) = l2;
            }
        }

        CP_WAIT1();
        __syncthreads();

        // ---- MMA on this warp's matrix ---------------------------------------
        const int aoff = S2_A + buf * S2_ABUF + which * 2 * S2_MAT;
        const int boff = S2_B + buf * S2_BBUF + which * 2 * S2_MAT;
        #pragma unroll
        for (int kt = 0; kt < 4; ++kt) {
            const int koff = kt * 32 + tq * 4;
            uint32_t ah[4][4], al[4][4];
            #pragma unroll
            for (int mi = 0; mi < 4; ++mi) {
                const char* ba = smem + aoff + (mi * 16 + g) * P1 + koff;
                ah[mi][0] = *(const uint32_t*)(ba);
                ah[mi][1] = *(const uint32_t*)(ba + 8 * P1);
                ah[mi][2] = *(const uint32_t*)(ba + 16);
                ah[mi][3] = *(const uint32_t*)(ba + 8 * P1 + 16);
                const char* bl_ = ba + S2_MAT;
                al[mi][0] = *(const uint32_t*)(bl_);
                al[mi][1] = *(const uint32_t*)(bl_ + 8 * P1);
                al[mi][2] = *(const uint32_t*)(bl_ + 16);
                al[mi][3] = *(const uint32_t*)(bl_ + 8 * P1 + 16);
            }
            #pragma unroll
            for (int ni = 0; ni < 2; ++ni) {
                const char* bb = smem + boff + (n0w + ni * 8 + g) * P1 + koff;
                uint32_t bh0 = *(const uint32_t*)(bb);
                uint32_t bh1 = *(const uint32_t*)(bb + 16);
                uint32_t bl0 = *(const uint32_t*)(bb + S2_MAT);
                uint32_t bl1 = *(const uint32_t*)(bb + S2_MAT + 16);
                #pragma unroll
                for (int mi = 0; mi < 4; ++mi) {
                    mma16816(acc[mi][ni], ah[mi][0], ah[mi][1], ah[mi][2], ah[mi][3], bh0, bh1);
                    mma16816(acc[mi][ni], ah[mi][0], ah[mi][1], ah[mi][2], ah[mi][3], bl0, bl1);
                    mma16816(acc[mi][ni], al[mi][0], al[mi][1], al[mi][2], al[mi][3], bh0, bh1);
                }
            }
        }
        __syncthreads();
    }

    // epilogue
    float* ztm = (float*)(smem + S2_ZT);
    float* ztv = ztm + 256;
    float* zrm = (float*)(smem + S2_ZR);
    float* zrv = zrm + 64;
    ztm[tid] = zm; ztv[tid] = zv;
    __syncthreads();
    if (tid < 64) {
        zrm[tid] = ztm[4 * tid] + ztm[4 * tid + 1] + ztm[4 * tid + 2] + ztm[4 * tid + 3];
        zrv[tid] = ztv[4 * tid] + ztv[4 * tid + 1] + ztv[4 * tid + 2] + ztv[4 * tid + 3];
    }
    __syncthreads();
    const float* zrow = which ? zrv : zrm;
    float* outw = which ? out_lv : out_mu;
    #pragma unroll
    for (int mi = 0; mi < 4; ++mi) {
        int r0 = mi * 16 + g;
        float iz0 = 1.f / zrow[r0];
        float iz1 = 1.f / zrow[r0 + 8];
        #pragma unroll
        for (int ni = 0; ni < 2; ++ni) {
            int col = n0w + ni * 8 + tq * 2;
            *(float2*)&outw[(size_t)(i0 + r0) * NLAT + col] =
                make_float2(acc[mi][ni][0] * iz0, acc[mi][ni][1] * iz0);
            *(float2*)&outw[(size_t)(i0 + r0 + 8) * NLAT + col] =
                make_float2(acc[mi][ni][2] * iz1, acc[mi][ni][3] * iz1);
        }
    }
}

// ---------------- z = mu + eps*exp(0.5*lv); logits = z @ Wc + bc ------------
__global__ __launch_bounds__(128)
void final_kernel(const float* __restrict__ mu, const float* __restrict__ lv,
                  const float* __restrict__ eps, const float* __restrict__ Wc,
                  const float* __restrict__ bc, float* __restrict__ logits)
{
    __shared__ float zs[8 * 64];
    const int tid = threadIdx.x;
    const int r0 = blockIdx.x * 8;
    #pragma unroll
    for (int l = tid; l < 8 * 64; l += 128) {
        int r = l >> 6, k = l & 63;
        size_t idx = (size_t)(r0 + r) * 64 + k;
        zs[l] = mu[idx] + eps[idx] * __expf(0.5f * lv[idx]);
    }
    __syncthreads();
    int r = tid >> 4, n = tid & 15;
    float acc = bc[n];
    #pragma unroll
    for (int k = 0; k < 64; ++k) acc += zs[r * 64 + k] * Wc[k * 16 + n];
    logits[(size_t)(r0 + r) * 16 + n] = acc;
}

// ------------------------------ launch --------------------------------------
extern "C" void kernel_launch(void* const* d_in, const int* in_sizes, int n_in,
                              void* d_out, int out_size)
{
    const float* x   = (const float*)d_in[0];
    const int*   adj = (const int*)  d_in[1];
    const float* eps = (const float*)d_in[2];
    const float* W1  = (const float*)d_in[3];
    const float* a1  = (const float*)d_in[4];
    const float* Wmu = (const float*)d_in[5];
    const float* amu = (const float*)d_in[6];
    const float* Wlv = (const float*)d_in[7];
    const float* alv = (const float*)d_in[8];
    const float* Wc  = (const float*)d_in[9];
    const float* bc  = (const float*)d_in[10];

    float* out    = (float*)d_out;
    float* logits = out;
    float* mu     = out + (size_t)N_NODES * NCLASS;
    float* lv     = mu  + (size_t)N_NODES * NLAT;

    float *Wh1, *h, *Whmu, *Whlv, *s1, *d1, *smu, *dmu, *slv, *dlv;
    float *E1, *F1, *Emu, *Fmu, *Elv, *Flv, *dmaxf;
    unsigned *dmaxu;
    __nv_bfloat16 *T1h, *T1l, *Tmh, *Tml, *Tvh, *Tvl;
    unsigned* adjb;
    cudaGetSymbolAddress((void**)&Wh1,  g_Wh1);
    cudaGetSymbolAddress((void**)&h,    g_h);
    cudaGetSymbolAddress((void**)&Whmu, g_Whmu);
    cudaGetSymbolAddress((void**)&Whlv, g_Whlv);
    cudaGetSymbolAddress((void**)&s1,   g_s1);
    cudaGetSymbolAddress((void**)&d1,   g_d1);
    cudaGetSymbolAddress((void**)&smu,  g_smu);
    cudaGetSymbolAddress((void**)&dmu,  g_dmu);
    cudaGetSymbolAddress((void**)&slv,  g_slv);
    cudaGetSymbolAddress((void**)&dlv,  g_dlv);
    cudaGetSymbolAddress((void**)&dmaxu, g_dmaxu);
    cudaGetSymbolAddress((void**)&dmaxf, g_dmaxf);
    cudaGetSymbolAddress((void**)&E1,   g_E1);
    cudaGetSymbolAddress((void**)&F1,   g_F1);
    cudaGetSymbolAddress((void**)&Emu,  g_Emu);
    cudaGetSymbolAddress((void**)&Fmu,  g_Fmu);
    cudaGetSymbolAddress((void**)&Elv,  g_Elv);
    cudaGetSymbolAddress((void**)&Flv,  g_Flv);
    cudaGetSymbolAddress((void**)&T1h,  g_T1h);
    cudaGetSymbolAddress((void**)&T1l,  g_T1l);
    cudaGetSymbolAddress((void**)&Tmh,  g_Tmh);
    cudaGetSymbolAddress((void**)&Tml,  g_Tml);
    cudaGetSymbolAddress((void**)&Tvh,  g_Tvh);
    cudaGetSymbolAddress((void**)&Tvl,  g_Tvl);
    cudaGetSymbolAddress((void**)&adjb, g_adjb);

    cudaFuncSetAttribute(attn1_kernel,  cudaFuncAttributeMaxDynamicSharedMemorySize, SMEM1);
    cudaFuncSetAttribute(attn23_kernel, cudaFuncAttributeMaxDynamicSharedMemorySize, SMEM2);

    init_kernel<<<1, 32>>>(dmaxu);
    pack_adj_kernel<<<(size_t)N_NODES * N_NODES / 256, 256>>>(adj, adjb);

    // layer 1
    gemm_kernel<<<dim3(NHID / 64, N_NODES / 64), 256>>>(x, W1, Wh1, N_NODES, NHID, NFEAT);
    sd_kernel<NHID><<<N_NODES * 32 / 256, 256>>>(Wh1, a1, s1, d1, dmaxu + 0);
    ef_kernel<<<N_NODES / 256, 256>>>(d1, dmaxu + 0, E1, F1, dmaxf + 0);
    tsplit_kernel<<<dim3(NHID / 32, N_NODES / 32), 256>>>(Wh1, T1h, T1l, NHID);
    attn1_kernel<<<N_NODES / 64, 256, SMEM1>>>(adjb, T1h, T1l, s1, d1, E1, F1, dmaxf + 0, h);

    // layer 2/3
    gemm_kernel<<<dim3(NLAT / 64, N_NODES / 64), 256>>>(h, Wmu, Whmu, N_NODES, NLAT, NHID);
    gemm_kernel<<<dim3(NLAT / 64, N_NODES / 64), 256>>>(h, Wlv, Whlv, N_NODES, NLAT, NHID);
    sd_kernel<NLAT><<<N_NODES * 32 / 256, 256>>>(Whmu, amu, smu, dmu, dmaxu + 1);
    sd_kernel<NLAT><<<N_NODES * 32 / 256, 256>>>(Whlv, alv, slv, dlv, dmaxu + 2);
    ef_kernel<<<N_NODES / 256, 256>>>(dmu, dmaxu + 1, Emu, Fmu, dmaxf + 1);
    ef_kernel<<<N_NODES / 256, 256>>>(dlv, dmaxu + 2, Elv, Flv, dmaxf + 2);
    tsplit_kernel<<<dim3(NLAT / 32, N_NODES / 32), 256>>>(Whmu, Tmh, Tml, NLAT);
    tsplit_kernel<<<dim3(NLAT / 32, N_NODES / 32), 256>>>(Whlv, Tvh, Tvl, NLAT);
    attn23_kernel<<<N_NODES / 64, 256, SMEM2>>>(adjb, Tmh, Tml, Tvh, Tvl,
                                                smu, dmu, slv, dlv,
                                                Emu, Fmu, Elv, Flv, dmaxf + 1, mu, lv);

    // reparameterize + classifier
    final_kernel<<<N_NODES / 8, 128>>>(mu, lv, eps, Wc, bc, logits);
}

// round 9
// speedup vs baseline: 1.1522x; 1.1522x over previous
#include <cuda_runtime.h>
#include <cuda_bf16.h>
#include <math.h>
#include <stdint.h>

#define N_NODES 8192
#define NFEAT   512
#define NHID    256
#define NLAT    64
#define NCLASS  16
#define ALPHA   0.2f
#define NWORDS  (N_NODES / 32)

// ------------------------------ device scratch ------------------------------
__device__ __align__(16) float g_Wh1 [N_NODES * NHID];
__device__ __align__(16) float g_h   [N_NODES * NHID];
__device__ __align__(16) float g_Whmu[N_NODES * NLAT];
__device__ __align__(16) float g_Whlv[N_NODES * NLAT];
__device__ __align__(16) __nv_bfloat16 g_T1h[NHID * N_NODES];
__device__ __align__(16) __nv_bfloat16 g_T1l[NHID * N_NODES];
__device__ __align__(16) __nv_bfloat16 g_Tmh[NLAT * N_NODES];
__device__ __align__(16) __nv_bfloat16 g_Tml[NLAT * N_NODES];
__device__ __align__(16) __nv_bfloat16 g_Tvh[NLAT * N_NODES];
__device__ __align__(16) __nv_bfloat16 g_Tvl[NLAT * N_NODES];
__device__ unsigned g_adjb[(size_t)N_NODES * NWORDS];
__device__ float g_s1[N_NODES], g_d1[N_NODES];
__device__ float g_smu[N_NODES], g_dmu[N_NODES];
__device__ float g_slv[N_NODES], g_dlv[N_NODES];
__device__ __align__(16) float g_E1[N_NODES],  g_F1[N_NODES];
__device__ __align__(16) float g_Emu[N_NODES], g_Fmu[N_NODES];
__device__ __align__(16) float g_Elv[N_NODES], g_Flv[N_NODES];
__device__ unsigned g_dmaxu[4];
__device__ float    g_dmaxf[4];

// ------------------------------ helpers -------------------------------------
__device__ __forceinline__ uint32_t smem_u32(const void* p) {
    uint32_t a;
    asm("{ .reg .u64 t; cvta.to.shared.u64 t, %1; cvt.u32.u64 %0, t; }"
        : "=r"(a) : "l"(p));
    return a;
}
__device__ __forceinline__ void cp_async16(uint32_t dst, const void* src) {
    asm volatile("cp.async.cg.shared.global [%0], [%1], 16;"
                 :: "r"(dst), "l"(src) : "memory");
}
#define CP_COMMIT() asm volatile("cp.async.commit_group;" ::: "memory")
#define CP_WAIT1()  asm volatile("cp.async.wait_group 1;"  ::: "memory")
#define CP_WAIT0()  asm volatile("cp.async.wait_group 0;"  ::: "memory")

__device__ __forceinline__ unsigned fenc(float x) {
    int ix = __float_as_int(x);
    return ix >= 0 ? ((unsigned)ix | 0x80000000u) : ~(unsigned)ix;
}
__device__ __forceinline__ float fdec(unsigned u) {
    int ix = (u & 0x80000000u) ? (int)(u & 0x7FFFFFFFu) : ~(int)u;
    return __int_as_float(ix);
}

// mma.sync m16n8k16 row.col bf16 -> f32 (HMMA on sm_103)
__device__ __forceinline__ void mma16816(float* c,
    uint32_t a0, uint32_t a1, uint32_t a2, uint32_t a3,
    uint32_t b0, uint32_t b1)
{
    asm volatile(
        "mma.sync.aligned.m16n8k16.row.col.f32.bf16.bf16.f32 "
        "{%0,%1,%2,%3}, {%4,%5,%6,%7}, {%8,%9}, {%0,%1,%2,%3};"
        : "+f"(c[0]), "+f"(c[1]), "+f"(c[2]), "+f"(c[3])
        : "r"(a0), "r"(a1), "r"(a2), "r"(a3), "r"(b0), "r"(b1));
}
__device__ __forceinline__ void ldsm_x4(uint32_t& r0, uint32_t& r1,
                                        uint32_t& r2, uint32_t& r3, uint32_t addr)
{
    asm volatile("ldmatrix.sync.aligned.m8n8.x4.shared.b16 {%0,%1,%2,%3}, [%4];"
                 : "=r"(r0), "=r"(r1), "=r"(r2), "=r"(r3) : "r"(addr));
}
__device__ __forceinline__ void ldsm_x2(uint32_t& r0, uint32_t& r1, uint32_t addr)
{
    asm volatile("ldmatrix.sync.aligned.m8n8.x2.shared.b16 {%0,%1}, [%2];"
                 : "=r"(r0), "=r"(r1) : "r"(addr));
}

// ------------------------------ utility kernels -----------------------------
__global__ void init_kernel(unsigned* dmaxu)
{
    if (threadIdx.x < 4) dmaxu[threadIdx.x] = 0u;
}

__global__ __launch_bounds__(256)
void pack_adj_kernel(const int* __restrict__ adj, unsigned* __restrict__ bits)
{
    size_t idx = (size_t)blockIdx.x * 256 + threadIdx.x;
    int v = adj[idx] > 0;
    unsigned b = __ballot_sync(0xffffffffu, v);
    if ((threadIdx.x & 31) == 0) bits[idx >> 5] = b;
}

__global__ __launch_bounds__(256)
void tsplit_kernel(const float* __restrict__ in,
                   __nv_bfloat16* __restrict__ hiT, __nv_bfloat16* __restrict__ loT,
                   int F)
{
    __shared__ float tile[32][33];
    int m0 = blockIdx.y * 32, f0 = blockIdx.x * 32;
    int x = threadIdx.x & 31, y = threadIdx.x >> 5;
    #pragma unroll
    for (int yy = 0; yy < 4; ++yy)
        tile[y + yy * 8][x] = in[(size_t)(m0 + y + yy * 8) * F + f0 + x];
    __syncthreads();
    #pragma unroll
    for (int yy = 0; yy < 4; ++yy) {
        float v = tile[x][y + yy * 8];
        __nv_bfloat16 hi = __float2bfloat16_rn(v);
        __nv_bfloat16 lo = __float2bfloat16_rn(v - __bfloat162float(hi));
        size_t o = (size_t)(f0 + y + yy * 8) * N_NODES + m0 + x;
        hiT[o] = hi; loT[o] = lo;
    }
}

__global__ __launch_bounds__(256)
void gemm_kernel(const float* __restrict__ A, const float* __restrict__ B,
                 float* __restrict__ C, int M, int N, int K)
{
    __shared__ float As[16][64];
    __shared__ float Bs[16][64];
    const int tid = threadIdx.x;
    const int tx = tid & 15, ty = tid >> 4;
    const int m0 = blockIdx.y * 64, n0 = blockIdx.x * 64;
    float acc[4][4] = {};
    for (int k0 = 0; k0 < K; k0 += 16) {
        {
            int m = tid >> 2, kq = (tid & 3) * 4;
            float4 v = *(const float4*)&A[(size_t)(m0 + m) * K + k0 + kq];
            As[kq + 0][m] = v.x; As[kq + 1][m] = v.y;
            As[kq + 2][m] = v.z; As[kq + 3][m] = v.w;
        }
        {
            int k = tid >> 4, nq = (tid & 15) * 4;
            *(float4*)&Bs[k][nq] = *(const float4*)&B[(size_t)(k0 + k) * N + n0 + nq];
        }
        __syncthreads();
        #pragma unroll
        for (int k = 0; k < 16; ++k) {
            float a[4], b[4];
            #pragma unroll
            for (int i = 0; i < 4; ++i) a[i] = As[k][ty * 4 + i];
            #pragma unroll
            for (int j = 0; j < 4; ++j) b[j] = Bs[k][tx * 4 + j];
            #pragma unroll
            for (int i = 0; i < 4; ++i)
                #pragma unroll
                for (int j = 0; j < 4; ++j)
                    acc[i][j] += a[i] * b[j];
        }
        __syncthreads();
    }
    #pragma unroll
    for (int i = 0; i < 4; ++i) {
        float4 v = make_float4(acc[i][0], acc[i][1], acc[i][2], acc[i][3]);
        *(float4*)&C[(size_t)(m0 + ty * 4 + i) * N + n0 + tx * 4] = v;
    }
}

template <int F>
__global__ __launch_bounds__(256)
void sd_kernel(const float* __restrict__ Wh, const float* __restrict__ a,
               float* __restrict__ s, float* __restrict__ d,
               unsigned* __restrict__ dmaxu)
{
    int warp = (blockIdx.x * blockDim.x + threadIdx.x) >> 5;
    int lane = threadIdx.x & 31;
    if (warp >= N_NODES) return;
    const float* row = Wh + (size_t)warp * F;
    float ss = 0.f, dd = 0.f;
    #pragma unroll
    for (int f = lane; f < F; f += 32) {
        float w = row[f];
        ss += w * a[f];
        dd += w * a[F + f];
    }
    #pragma unroll
    for (int o = 16; o; o >>= 1) {
        ss += __shfl_down_sync(0xffffffffu, ss, o);
        dd += __shfl_down_sync(0xffffffffu, dd, o);
    }
    if (lane == 0) {
        s[warp] = ss; d[warp] = dd;
        atomicMax(dmaxu, fenc(dd));
    }
}

__global__ __launch_bounds__(256)
void ef_kernel(const float* __restrict__ d, const unsigned* __restrict__ dmaxu,
               float* __restrict__ E, float* __restrict__ F,
               float* __restrict__ dmaxf)
{
    float dm = fdec(*dmaxu);
    int i = blockIdx.x * 256 + threadIdx.x;
    float v = d[i] - dm;
    E[i] = __expf(v);
    F[i] = __expf(ALPHA * v);
    if (i == 0) *dmaxf = dm;
}

// =============================================================================
// attn1: h = ELU( softmax(mask(leaky(s_i+d_j))) @ Wh1 )   F=256, HMMA bf16x3
// CTA 64 rows, 512 threads (16 warps; warp w -> cols [16w,16w+16)).
// j-tile 64 double-buffered; ldmatrix fragment loads; 144B row pitch.
// =============================================================================
static constexpr int P1      = 144;
static constexpr int S1_B    = 0;          // 2 buf x [hi 256x144 | lo 256x144]
static constexpr int S1_BBUF = 73728;
static constexpr int S1_BLOO = 36864;
static constexpr int S1_A    = 147456;     // 2 buf x [hi 64x144 | lo 64x144]
static constexpr int S1_ABUF = 18432;
static constexpr int S1_ALOO = 9216;
static constexpr int S1_ZT   = 184320;     // 512 floats
static constexpr int S1_ZR   = 186368;     // 64 floats
static constexpr int SMEM1   = 186624;

__global__ __launch_bounds__(512, 1)
void attn1_kernel(const unsigned* __restrict__ adjb,
                  const __nv_bfloat16* __restrict__ Bh,
                  const __nv_bfloat16* __restrict__ Bl,
                  const float* __restrict__ svec, const float* __restrict__ dvec,
                  const float* __restrict__ EJ, const float* __restrict__ FJ,
                  const float* __restrict__ dmaxp, float* __restrict__ outp)
{
    extern __shared__ __align__(16) char smem[];
    const uint32_t sb = smem_u32(smem);
    const int tid = threadIdx.x, warp = tid >> 5, lane = tid & 31;
    const int g = lane >> 2, tq = lane & 3;
    const int i0 = blockIdx.x * 64;
    const int n0w = warp * 16;

    // ldmatrix per-lane offsets
    const uint32_t a_lane = ((lane & 7) + ((lane >> 3) & 1) * 8) * P1 + ((lane >> 4) & 1) * 16;
    const uint32_t b_lane = ((lane & 7) + ((lane >> 4) & 1) * 8) * P1 + ((lane >> 3) & 1) * 16;

    const int r = tid >> 3, q = tid & 7;
    const float sv = svec[i0 + r];
    const float mv = sv + *dmaxp;
    const float m_r = mv > 0.f ? mv : ALPHA * mv;
    const float RA = __expf(mv - m_r);
    const float RB = __expf(ALPHA * mv - m_r);
    float zacc = 0.f;

    float acc[4][2][4];
    #pragma unroll
    for (int a = 0; a < 4; ++a)
        #pragma unroll
        for (int b = 0; b < 2; ++b)
            #pragma unroll
            for (int c = 0; c < 4; ++c) acc[a][b][c] = 0.f;

    const size_t row_adj = (size_t)(i0 + r) * NWORDS;

    // prologue: stage B tile 0 into buffer 0
    for (int c = tid; c < 4096; c += 512) {
        int mat = c >> 11, f = (c >> 3) & 255, ch = c & 7;
        uint32_t dst = sb + S1_B + mat * S1_BLOO + f * P1 + ch * 16;
        const __nv_bfloat16* src = (mat ? Bl : Bh) + (size_t)f * N_NODES + ch * 8;
        cp_async16(dst, src);
    }
    CP_COMMIT();

    for (int t = 0; t < N_NODES / 64; ++t) {
        const int j0 = t * 64;
        const int buf = t & 1;

        if (t + 1 < N_NODES / 64) {
            const int j1 = j0 + 64;
            const uint32_t bb = sb + S1_B + (buf ^ 1) * S1_BBUF;
            for (int c = tid; c < 4096; c += 512) {
                int mat = c >> 11, f = (c >> 3) & 255, ch = c & 7;
                uint32_t dst = bb + mat * S1_BLOO + f * P1 + ch * 16;
                const __nv_bfloat16* src = (mat ? Bl : Bh) + (size_t)f * N_NODES + j1 + ch * 8;
                cp_async16(dst, src);
            }
        }
        CP_COMMIT();

        // ---- P-gen into A[buf]: thread covers (r, j in [q*8, q*8+8)) --------
        {
            unsigned w = adjb[row_adj + (j0 >> 5) + (q >> 2)];
            unsigned bits = w >> ((q & 3) * 8);
            char* ahi = smem + S1_A + buf * S1_ABUF + r * P1;
            char* alo = ahi + S1_ALOO;
            const int jb = q * 8;
            #pragma unroll
            for (int qq = 0; qq < 8; qq += 2) {
                int jl = jb + qq;
                int b0 = (bits >> qq) & 1;
                int b1 = (bits >> (qq + 1)) & 1;
                float d0 = dvec[j0 + jl], d1 = dvec[j0 + jl + 1];
                float p0 = b0 ? ((sv + d0 > 0.f) ? RA * EJ[j0 + jl]     : RB * FJ[j0 + jl])     : 0.f;
                float p1 = b1 ? ((sv + d1 > 0.f) ? RA * EJ[j0 + jl + 1] : RB * FJ[j0 + jl + 1]) : 0.f;
                zacc += p0 + p1;
                __nv_bfloat162 h2 = __floats2bfloat162_rn(p0, p1);
                float l0 = p0 - __bfloat162float(h2.x);
                float l1 = p1 - __bfloat162float(h2.y);
                __nv_bfloat162 lo2 = __floats2bfloat162_rn(l0, l1);
                *(__nv_bfloat162*)(ahi + jl * 2) = h2;
                *(__nv_bfloat162*)(alo + jl * 2) = lo2;
            }
        }

        CP_WAIT1();
        __syncthreads();

        // ---- MMA on buffer buf (ldmatrix fragment loads) ----------------------
        const uint32_t abase = sb + S1_A + buf * S1_ABUF + a_lane;
        const uint32_t bbase = sb + S1_B + buf * S1_BBUF + n0w * P1 + b_lane;
        #pragma unroll
        for (int kt = 0; kt < 4; ++kt) {
            const int koff = kt * 32;
            uint32_t ah[4][4], al[4][4];
            #pragma unroll
            for (int mi = 0; mi < 4; ++mi)
                ldsm_x4(ah[mi][0], ah[mi][1], ah[mi][2], ah[mi][3],
                        abase + mi * (16 * P1) + koff);
            #pragma unroll
            for (int mi = 0; mi < 4; ++mi)
                ldsm_x4(al[mi][0], al[mi][1], al[mi][2], al[mi][3],
                        abase + S1_ALOO + mi * (16 * P1) + koff);
            uint32_t bh0, bh1, bh2, bh3, bl0, bl1, bl2, bl3;
            ldsm_x4(bh0, bh1, bh2, bh3, bbase + koff);
            ldsm_x4(bl0, bl1, bl2, bl3, bbase + S1_BLOO + koff);
            #pragma unroll
            for (int mi = 0; mi < 4; ++mi) {
                mma16816(acc[mi][0], ah[mi][0], ah[mi][1], ah[mi][2], ah[mi][3], bh0, bh1);
                mma16816(acc[mi][0], ah[mi][0], ah[mi][1], ah[mi][2], ah[mi][3], bl0, bl1);
                mma16816(acc[mi][0], al[mi][0], al[mi][1], al[mi][2], al[mi][3], bh0, bh1);
                mma16816(acc[mi][1], ah[mi][0], ah[mi][1], ah[mi][2], ah[mi][3], bh2, bh3);
                mma16816(acc[mi][1], ah[mi][0], ah[mi][1], ah[mi][2], ah[mi][3], bl2, bl3);
                mma16816(acc[mi][1], al[mi][0], al[mi][1], al[mi][2], al[mi][3], bh2, bh3);
            }
        }
        __syncthreads();
    }

    // ---- epilogue --------------------------------------------------------------
    float* zt = (float*)(smem + S1_ZT);
    float* zr = (float*)(smem + S1_ZR);
    zt[tid] = zacc;
    __syncthreads();
    if (tid < 64) {
        float z = 0.f;
        #pragma unroll
        for (int k = 0; k < 8; ++k) z += zt[8 * tid + k];
        zr[tid] = z;
    }
    __syncthreads();
    #pragma unroll
    for (int mi = 0; mi < 4; ++mi) {
        int r0 = mi * 16 + g;
        float iz0 = 1.f / zr[r0];
        float iz1 = 1.f / zr[r0 + 8];
        #pragma unroll
        for (int ni = 0; ni < 2; ++ni) {
            int col = n0w + ni * 8 + tq * 2;
            float v0 = acc[mi][ni][0] * iz0; v0 = v0 > 0.f ? v0 : expm1f(v0);
            float v1 = acc[mi][ni][1] * iz0; v1 = v1 > 0.f ? v1 : expm1f(v1);
            float v2 = acc[mi][ni][2] * iz1; v2 = v2 > 0.f ? v2 : expm1f(v2);
            float v3 = acc[mi][ni][3] * iz1; v3 = v3 > 0.f ? v3 : expm1f(v3);
            *(float2*)&outp[(size_t)(i0 + r0) * NHID + col]     = make_float2(v0, v1);
            *(float2*)&outp[(size_t)(i0 + r0 + 8) * NHID + col] = make_float2(v2, v3);
        }
    }
}

// =============================================================================
// attn23: fused mu & lv attention, F=64 each. 512 threads.
// warps 0-7: mu cols [8w..8w+8); warps 8-15: lv.
// =============================================================================
static constexpr int S2_B    = 0;          // 2 buf x 4 mats x 64x144
static constexpr int S2_BBUF = 36864;
static constexpr int S2_A    = 73728;
static constexpr int S2_ABUF = 36864;
static constexpr int S2_MAT  = 9216;
static constexpr int S2_ZT   = 147456;     // 2 x 512 floats
static constexpr int S2_ZR   = 151552;     // 2 x 64 floats
static constexpr int SMEM2   = 152064;

__global__ __launch_bounds__(512, 1)
void attn23_kernel(const unsigned* __restrict__ adjb,
                   const __nv_bfloat16* __restrict__ Bmh, const __nv_bfloat16* __restrict__ Bml,
                   const __nv_bfloat16* __restrict__ Bvh, const __nv_bfloat16* __restrict__ Bvl,
                   const float* __restrict__ smuv, const float* __restrict__ dmuv,
                   const float* __restrict__ slvv, const float* __restrict__ dlvv,
                   const float* __restrict__ Em, const float* __restrict__ Fm,
                   const float* __restrict__ Ev, const float* __restrict__ Fv,
                   const float* __restrict__ dmaxp,   // [0]=mu, [1]=lv
                   float* __restrict__ out_mu, float* __restrict__ out_lv)
{
    extern __shared__ __align__(16) char smem[];
    const uint32_t sb = smem_u32(smem);
    const int tid = threadIdx.x, warp = tid >> 5, lane = tid & 31;
    const int g = lane >> 2, tq = lane & 3;
    const int i0 = blockIdx.x * 64;
    const int which = warp >> 3;          // 0 = mu, 1 = lv
    const int n0w = (warp & 7) * 8;

    const uint32_t a_lane = ((lane & 7) + ((lane >> 3) & 1) * 8) * P1 + ((lane >> 4) & 1) * 16;
    const uint32_t b_lane = (lane & 7) * P1 + ((lane >> 3) & 1) * 16;   // x2 uses lanes 0-15

    const int r = tid >> 3, q = tid & 7;
    const float svm = smuv[i0 + r], svv = slvv[i0 + r];
    const float mvm = svm + dmaxp[0], mvv = svv + dmaxp[1];
    const float mm = mvm > 0.f ? mvm : ALPHA * mvm;
    const float ml = mvv > 0.f ? mvv : ALPHA * mvv;
    const float RAm = __expf(mvm - mm), RBm = __expf(ALPHA * mvm - mm);
    const float RAv = __expf(mvv - ml), RBv = __expf(ALPHA * mvv - ml);
    float zm = 0.f, zv = 0.f;

    float acc[4][4];
    #pragma unroll
    for (int a = 0; a < 4; ++a)
        #pragma unroll
        for (int c = 0; c < 4; ++c) acc[a][c] = 0.f;

    const size_t row_adj = (size_t)(i0 + r) * NWORDS;

    // prologue
    for (int c = tid; c < 2048; c += 512) {
        int mat = c >> 9, f = (c >> 3) & 63, ch = c & 7;
        uint32_t dst = sb + S2_B + mat * S2_MAT + f * P1 + ch * 16;
        const __nv_bfloat16* src = (mat == 0 ? Bmh : mat == 1 ? Bml : mat == 2 ? Bvh : Bvl)
                                   + (size_t)f * N_NODES + ch * 8;
        cp_async16(dst, src);
    }
    CP_COMMIT();

    for (int t = 0; t < N_NODES / 64; ++t) {
        const int j0 = t * 64;
        const int buf = t & 1;

        if (t + 1 < N_NODES / 64) {
            const int j1 = j0 + 64;
            const uint32_t bbs = sb + S2_B + (buf ^ 1) * S2_BBUF;
            for (int c = tid; c < 2048; c += 512) {
                int mat = c >> 9, f = (c >> 3) & 63, ch = c & 7;
                uint32_t dst = bbs + mat * S2_MAT + f * P1 + ch * 16;
                const __nv_bfloat16* src = (mat == 0 ? Bmh : mat == 1 ? Bml : mat == 2 ? Bvh : Bvl)
                                           + (size_t)f * N_NODES + j1 + ch * 8;
                cp_async16(dst, src);
            }
        }
        CP_COMMIT();

        // ---- P-gen: both matrices, thread covers (r, j in [q*8, q*8+8)) -----
        {
            unsigned w = adjb[row_adj + (j0 >> 5) + (q >> 2)];
            unsigned bits = w >> ((q & 3) * 8);
            char* amh = smem + S2_A + buf * S2_ABUF + r * P1;
            char* aml = amh + S2_MAT;
            char* avh = amh + 2 * S2_MAT;
            char* avl = amh + 3 * S2_MAT;
            const int jb = q * 8;
            #pragma unroll
            for (int qq = 0; qq < 8; qq += 2) {
                int jl = jb + qq;
                int b0 = (bits >> qq) & 1;
                int b1 = (bits >> (qq + 1)) & 1;

                float d0 = dmuv[j0 + jl], d1 = dmuv[j0 + jl + 1];
                float p0 = b0 ? ((svm + d0 > 0.f) ? RAm * Em[j0 + jl]     : RBm * Fm[j0 + jl])     : 0.f;
                float p1 = b1 ? ((svm + d1 > 0.f) ? RAm * Em[j0 + jl + 1] : RBm * Fm[j0 + jl + 1]) : 0.f;
                zm += p0 + p1;
                __nv_bfloat162 h2 = __floats2bfloat162_rn(p0, p1);
                __nv_bfloat162 l2 = __floats2bfloat162_rn(p0 - __bfloat162float(h2.x),
                                                          p1 - __bfloat162float(h2.y));
                *(__nv_bfloat162*)(amh + jl * 2) = h2;
                *(__nv_bfloat162*)(aml + jl * 2) = l2;

                d0 = dlvv[j0 + jl]; d1 = dlvv[j0 + jl + 1];
                p0 = b0 ? ((svv + d0 > 0.f) ? RAv * Ev[j0 + jl]     : RBv * Fv[j0 + jl])     : 0.f;
                p1 = b1 ? ((svv + d1 > 0.f) ? RAv * Ev[j0 + jl + 1] : RBv * Fv[j0 + jl + 1]) : 0.f;
                zv += p0 + p1;
                h2 = __floats2bfloat162_rn(p0, p1);
                l2 = __floats2bfloat162_rn(p0 - __bfloat162float(h2.x),
                                           p1 - __bfloat162float(h2.y));
                *(__nv_bfloat162*)(avh + jl * 2) = h2;
                *(__nv_bfloat162*)(avl + jl * 2) = l2;
            }
        }

        CP_WAIT1();
        __syncthreads();

        // ---- MMA on this warp's matrix ---------------------------------------
        const uint32_t abase = sb + S2_A + buf * S2_ABUF + which * 2 * S2_MAT + a_lane;
        const uint32_t bbase = sb + S2_B + buf * S2_BBUF + which * 2 * S2_MAT
                             + n0w * P1 + b_lane;
        #pragma unroll
        for (int kt = 0; kt < 4; ++kt) {
            const int koff = kt * 32;
            uint32_t ah[4][4], al[4][4];
            #pragma unroll
            for (int mi = 0; mi < 4; ++mi)
                ldsm_x4(ah[mi][0], ah[mi][1], ah[mi][2], ah[mi][3],
                        abase + mi * (16 * P1) + koff);
            #pragma unroll
            for (int mi = 0; mi < 4; ++mi)
                ldsm_x4(al[mi][0], al[mi][1], al[mi][2], al[mi][3],
                        abase + S2_MAT + mi * (16 * P1) + koff);
            uint32_t bh0, bh1, bl0, bl1;
            ldsm_x2(bh0, bh1, bbase + koff);
            ldsm_x2(bl0, bl1, bbase + S2_MAT + koff);
            #pragma unroll
            for (int mi = 0; mi < 4; ++mi) {
                mma16816(acc[mi], ah[mi][0], ah[mi][1], ah[mi][2], ah[mi][3], bh0, bh1);
                mma16816(acc[mi], ah[mi][0], ah[mi][1], ah[mi][2], ah[mi][3], bl0, bl1);
                mma16816(acc[mi], al[mi][0], al[mi][1], al[mi][2], al[mi][3], bh0, bh1);
            }
        }
        __syncthreads();
    }

    // epilogue
    float* ztm = (float*)(smem + S2_ZT);
    float* ztv = ztm + 512;
    float* zrm = (float*)(smem + S2_ZR);
    float* zrv = zrm + 64;
    ztm[tid] = zm; ztv[tid] = zv;
    __syncthreads();
    if (tid < 64) {
        float a = 0.f, b = 0.f;
        #pragma unroll
        for (int k = 0; k < 8; ++k) { a += ztm[8 * tid + k]; b += ztv[8 * tid + k]; }
        zrm[tid] = a; zrv[tid] = b;
    }
    __syncthreads();
    const float* zrow = which ? zrv : zrm;
    float* outw = which ? out_lv : out_mu;
    #pragma unroll
    for (int mi = 0; mi < 4; ++mi) {
        int r0 = mi * 16 + g;
        float iz0 = 1.f / zrow[r0];
        float iz1 = 1.f / zrow[r0 + 8];
        int col = n0w + tq * 2;
        *(float2*)&outw[(size_t)(i0 + r0) * NLAT + col] =
            make_float2(acc[mi][0] * iz0, acc[mi][1] * iz0);
        *(float2*)&outw[(size_t)(i0 + r0 + 8) * NLAT + col] =
            make_float2(acc[mi][2] * iz1, acc[mi][3] * iz1);
    }
}

// ---------------- z = mu + eps*exp(0.5*lv); logits = z @ Wc + bc ------------
__global__ __launch_bounds__(128)
void final_kernel(const float* __restrict__ mu, const float* __restrict__ lv,
                  const float* __restrict__ eps, const float* __restrict__ Wc,
                  const float* __restrict__ bc, float* __restrict__ logits)
{
    __shared__ float zs[8 * 64];
    const int tid = threadIdx.x;
    const int r0 = blockIdx.x * 8;
    #pragma unroll
    for (int l = tid; l < 8 * 64; l += 128) {
        int r = l >> 6, k = l & 63;
        size_t idx = (size_t)(r0 + r) * 64 + k;
        zs[l] = mu[idx] + eps[idx] * __expf(0.5f * lv[idx]);
    }
    __syncthreads();
    int r = tid >> 4, n = tid & 15;
    float acc = bc[n];
    #pragma unroll
    for (int k = 0; k < 64; ++k) acc += zs[r * 64 + k] * Wc[k * 16 + n];
    logits[(size_t)(r0 + r) * 16 + n] = acc;
}

// ------------------------------ launch --------------------------------------
extern "C" void kernel_launch(void* const* d_in, const int* in_sizes, int n_in,
                              void* d_out, int out_size)
{
    const float* x   = (const float*)d_in[0];
    const int*   adj = (const int*)  d_in[1];
    const float* eps = (const float*)d_in[2];
    const float* W1  = (const float*)d_in[3];
    const float* a1  = (const float*)d_in[4];
    const float* Wmu = (const float*)d_in[5];
    const float* amu = (const float*)d_in[6];
    const float* Wlv = (const float*)d_in[7];
    const float* alv = (const float*)d_in[8];
    const float* Wc  = (const float*)d_in[9];
    const float* bc  = (const float*)d_in[10];

    float* out    = (float*)d_out;
    float* logits = out;
    float* mu     = out + (size_t)N_NODES * NCLASS;
    float* lv     = mu  + (size_t)N_NODES * NLAT;

    float *Wh1, *h, *Whmu, *Whlv, *s1, *d1, *smu, *dmu, *slv, *dlv;
    float *E1, *F1, *Emu, *Fmu, *Elv, *Flv, *dmaxf;
    unsigned *dmaxu;
    __nv_bfloat16 *T1h, *T1l, *Tmh, *Tml, *Tvh, *Tvl;
    unsigned* adjb;
    cudaGetSymbolAddress((void**)&Wh1,  g_Wh1);
    cudaGetSymbolAddress((void**)&h,    g_h);
    cudaGetSymbolAddress((void**)&Whmu, g_Whmu);
    cudaGetSymbolAddress((void**)&Whlv, g_Whlv);
    cudaGetSymbolAddress((void**)&s1,   g_s1);
    cudaGetSymbolAddress((void**)&d1,   g_d1);
    cudaGetSymbolAddress((void**)&smu,  g_smu);
    cudaGetSymbolAddress((void**)&dmu,  g_dmu);
    cudaGetSymbolAddress((void**)&slv,  g_slv);
    cudaGetSymbolAddress((void**)&dlv,  g_dlv);
    cudaGetSymbolAddress((void**)&dmaxu, g_dmaxu);
    cudaGetSymbolAddress((void**)&dmaxf, g_dmaxf);
    cudaGetSymbolAddress((void**)&E1,   g_E1);
    cudaGetSymbolAddress((void**)&F1,   g_F1);
    cudaGetSymbolAddress((void**)&Emu,  g_Emu);
    cudaGetSymbolAddress((void**)&Fmu,  g_Fmu);
    cudaGetSymbolAddress((void**)&Elv,  g_Elv);
    cudaGetSymbolAddress((void**)&Flv,  g_Flv);
    cudaGetSymbolAddress((void**)&T1h,  g_T1h);
    cudaGetSymbolAddress((void**)&T1l,  g_T1l);
    cudaGetSymbolAddress((void**)&Tmh,  g_Tmh);
    cudaGetSymbolAddress((void**)&Tml,  g_Tml);
    cudaGetSymbolAddress((void**)&Tvh,  g_Tvh);
    cudaGetSymbolAddress((void**)&Tvl,  g_Tvl);
    cudaGetSymbolAddress((void**)&adjb, g_adjb);

    cudaFuncSetAttribute(attn1_kernel,  cudaFuncAttributeMaxDynamicSharedMemorySize, SMEM1);
    cudaFuncSetAttribute(attn23_kernel, cudaFuncAttributeMaxDynamicSharedMemorySize, SMEM2);

    init_kernel<<<1, 32>>>(dmaxu);
    pack_adj_kernel<<<(size_t)N_NODES * N_NODES / 256, 256>>>(adj, adjb);

    // layer 1
    gemm_kernel<<<dim3(NHID / 64, N_NODES / 64), 256>>>(x, W1, Wh1, N_NODES, NHID, NFEAT);
    sd_kernel<NHID><<<N_NODES * 32 / 256, 256>>>(Wh1, a1, s1, d1, dmaxu + 0);
    ef_kernel<<<N_NODES / 256, 256>>>(d1, dmaxu + 0, E1, F1, dmaxf + 0);
    tsplit_kernel<<<dim3(NHID / 32, N_NODES / 32), 256>>>(Wh1, T1h, T1l, NHID);
    attn1_kernel<<<N_NODES / 64, 512, SMEM1>>>(adjb, T1h, T1l, s1, d1, E1, F1, dmaxf + 0, h);

    // layer 2/3
    gemm_kernel<<<dim3(NLAT / 64, N_NODES / 64), 256>>>(h, Wmu, Whmu, N_NODES, NLAT, NHID);
    gemm_kernel<<<dim3(NLAT / 64, N_NODES / 64), 256>>>(h, Wlv, Whlv, N_NODES, NLAT, NHID);
    sd_kernel<NLAT><<<N_NODES * 32 / 256, 256>>>(Whmu, amu, smu, dmu, dmaxu + 1);
    sd_kernel<NLAT><<<N_NODES * 32 / 256, 256>>>(Whlv, alv, slv, dlv, dmaxu + 2);
    ef_kernel<<<N_NODES / 256, 256>>>(dmu, dmaxu + 1, Emu, Fmu, dmaxf + 1);
    ef_kernel<<<N_NODES / 256, 256>>>(dlv, dmaxu + 2, Elv, Flv, dmaxf + 2);
    tsplit_kernel<<<dim3(NLAT / 32, N_NODES / 32), 256>>>(Whmu, Tmh, Tml, NLAT);
    tsplit_kernel<<<dim3(NLAT / 32, N_NODES / 32), 256>>>(Whlv, Tvh, Tvl, NLAT);
    attn23_kernel<<<N_NODES / 64, 512, SMEM2>>>(adjb, Tmh, Tml, Tvh, Tvl,
                                                smu, dmu, slv, dlv,
                                                Emu, Fmu, Elv, Flv, dmaxf + 1, mu, lv);

    // reparameterize + classifier
    final_kernel<<<N_NODES / 8, 128>>>(mu, lv, eps, Wc, bc, logits);
}